// round 12
// baseline (speedup 1.0000x reference)
#include <cuda_runtime.h>
#include <cuda_bf16.h>
#include <math.h>
#include <stdint.h>

#define CNUM 32
#define KS   3
#define RS   11
#define BAT  16
#define HW   256
#define POWER_IT 3

// 3x3-step GEMM geometry
#define XS3   20                 // u32 stride per window column (16 used)
#define WCOL3 258                // window columns (256 + 2 halo)
#define WROW3 (WCOL3*XS3)        // 5160 u32 per (term,row)
#define WS3   148                // u32 stride per weight row (144 used)
#define WT3   (32*WS3)           // 4736 u32 per weight term
#define SM3_U32 (2*4*WROW3 + 2*WT3)   // 50752 u32 = 203008 B

// ---------------------------------------------------------------------------
// Device scratch
// ---------------------------------------------------------------------------
__device__ float g_sk[CNUM*CNUM*KS*KS];
__device__ __align__(16) unsigned short g_xhi[(size_t)BAT*HW*HW*CNUM];
__device__ __align__(16) unsigned short g_xlo[(size_t)BAT*HW*HW*CNUM];
__device__ __align__(16) unsigned short g_u0h[(size_t)BAT*HW*HW*CNUM];
__device__ __align__(16) unsigned short g_u0l[(size_t)BAT*HW*HW*CNUM];
__device__ __align__(16) unsigned short g_u1h[(size_t)BAT*HW*HW*CNUM];
__device__ __align__(16) unsigned short g_u1l[(size_t)BAT*HW*HW*CNUM];
// 3x3 step weights: [step 0..4][term hi/lo][o=32][WS3 u32]
__device__ uint32_t g_wm3[5*2*32*WS3];

// ---------------------------------------------------------------------------
// MMA / ldmatrix helpers (base-target; validated R5-R7)
// ---------------------------------------------------------------------------
__device__ __forceinline__ void mma_bf16(float* c, const uint32_t* a,
                                         const uint32_t* b) {
    asm volatile(
        "mma.sync.aligned.m16n8k16.row.col.f32.bf16.bf16.f32 "
        "{%0,%1,%2,%3}, {%4,%5,%6,%7}, {%8,%9}, {%0,%1,%2,%3};\n"
        : "+f"(c[0]), "+f"(c[1]), "+f"(c[2]), "+f"(c[3])
        : "r"(a[0]), "r"(a[1]), "r"(a[2]), "r"(a[3]),
          "r"(b[0]), "r"(b[1]));
}
__device__ __forceinline__ void ldsm_x4(uint32_t* r, uint32_t addr) {
    asm volatile(
        "ldmatrix.sync.aligned.m8n8.x4.shared.b16 {%0,%1,%2,%3}, [%4];"
        : "=r"(r[0]), "=r"(r[1]), "=r"(r[2]), "=r"(r[3]) : "r"(addr));
}
__device__ __forceinline__ uint32_t smem_u32(const void* p) {
    uint32_t a;
    asm("{ .reg .u64 t; cvta.to.shared.u64 t, %1; cvt.u32.u64 %0, t; }"
        : "=r"(a) : "l"(p));
    return a;
}
__device__ __forceinline__ float bf16_lo(uint32_t u) {
    return __bfloat162float(__ushort_as_bfloat16((unsigned short)(u & 0xFFFF)));
}
__device__ __forceinline__ float bf16_hi(uint32_t u) {
    return __bfloat162float(__ushort_as_bfloat16((unsigned short)(u >> 16)));
}
__device__ __forceinline__ uint32_t pack_split_hi(float v0, float v1) {
    unsigned short h0 = __bfloat16_as_ushort(__float2bfloat16(v0));
    unsigned short h1 = __bfloat16_as_ushort(__float2bfloat16(v1));
    return (uint32_t)h0 | ((uint32_t)h1 << 16);
}
__device__ __forceinline__ uint32_t pack_split_lo(float v0, float v1) {
    float r0 = v0 - __bfloat162float(__float2bfloat16(v0));
    float r1 = v1 - __bfloat162float(__float2bfloat16(v1));
    unsigned short h0 = __bfloat16_as_ushort(__float2bfloat16(r0));
    unsigned short h1 = __bfloat16_as_ushort(__float2bfloat16(r1));
    return (uint32_t)h0 | ((uint32_t)h1 << 16);
}

__device__ __forceinline__ const uint32_t* sel_hi(int s) {
    return (s == 0) ? (const uint32_t*)g_xhi
         : (s == 1) ? (const uint32_t*)g_u0h : (const uint32_t*)g_u1h;
}
__device__ __forceinline__ const uint32_t* sel_lo(int s) {
    return (s == 0) ? (const uint32_t*)g_xlo
         : (s == 1) ? (const uint32_t*)g_u0l : (const uint32_t*)g_u1l;
}
__device__ __forceinline__ uint32_t* sel_hi_w(int s) {
    return (s == 1) ? (uint32_t*)g_u0h : (uint32_t*)g_u1h;
}
__device__ __forceinline__ uint32_t* sel_lo_w(int s) {
    return (s == 1) ? (uint32_t*)g_u0l : (uint32_t*)g_u1l;
}

// ---------------------------------------------------------------------------
// Block reduce via warp shuffles: 3 syncs instead of 11.
// ---------------------------------------------------------------------------
__device__ __forceinline__ float blk_reduce(float v, float* red) {
    int wid = threadIdx.x >> 5, lane = threadIdx.x & 31;
    #pragma unroll
    for (int o = 16; o; o >>= 1) v += __shfl_down_sync(0xFFFFFFFFu, v, o);
    if (lane == 0) red[wid] = v;
    __syncthreads();
    if (wid == 0) {
        float s = (lane < ((int)blockDim.x >> 5)) ? red[lane] : 0.f;
        #pragma unroll
        for (int o = 16; o; o >>= 1) s += __shfl_down_sync(0xFFFFFFFFu, s, o);
        if (lane == 0) red[0] = s;
    }
    __syncthreads();
    float r = red[0];
    __syncthreads();
    return r;
}
__device__ __forceinline__ void blk_l2n(float* a, int n, float* red) {
    int tid = threadIdx.x;
    float p = 0.f;
    for (int i = tid; i < n; i += 1024) p += a[i] * a[i];
    float s = blk_reduce(p, red);
    float sc = 1.0f / (sqrtf(s) + 1e-12f);
    for (int i = tid; i < n; i += 1024) a[i] *= sc;
    __syncthreads();
}

__global__ void __launch_bounds__(1024) prep_ff(
    const float* __restrict__ raw,
    const float* __restrict__ u1i, const float* __restrict__ u2i,
    const float* __restrict__ u3i, const float* __restrict__ u4i)
{
    __shared__ float sk[CNUM*CNUM*KS*KS];
    __shared__ float su1[96], sv1[96], su2[96], sv2[96];
    __shared__ float su3[288], sv3[32], su4[288], sv4[32];
    __shared__ float red[32];
    int tid = threadIdx.x;

    for (int i = tid; i < 9216; i += 1024) {
        int o = i / 288, r = i % 288;
        int c = r / 9, h = (r % 9) / 3, w = r % 3;
        sk[i] = raw[i] - raw[((c*32 + o)*3 + (2 - h))*3 + (2 - w)];
    }
    if (tid < 96)  su1[tid] = u1i[tid];
    if (tid < 96)  su2[tid] = u2i[tid];
    if (tid < 288) su3[tid] = u3i[tid];
    if (tid < 288) su4[tid] = u4i[tid];
    __syncthreads();

    blk_l2n(su1, 96, red);  blk_l2n(su2, 96, red);
    blk_l2n(su3, 288, red); blk_l2n(su4, 288, red);

    for (int it = 0; it < POWER_IT; it++) {
        if (tid < 96) {
            int o = tid / 3, h = tid % 3; float s = 0.f;
            for (int c = 0; c < 32; c++)
                for (int w = 0; w < 3; w++)
                    s += sk[((o*32 + c)*3 + h)*3 + w] * su1[c*3 + w];
            sv1[tid] = s;
        }
        __syncthreads(); blk_l2n(sv1, 96, red);
        if (tid < 96) {
            int c = tid / 3, w = tid % 3; float s = 0.f;
            for (int o = 0; o < 32; o++)
                for (int h = 0; h < 3; h++)
                    s += sk[((o*32 + c)*3 + h)*3 + w] * sv1[o*3 + h];
            su1[tid] = s;
        }
        __syncthreads(); blk_l2n(su1, 96, red);

        if (tid < 96) {
            int o = tid / 3, w = tid % 3; float s = 0.f;
            for (int c = 0; c < 32; c++)
                for (int h = 0; h < 3; h++)
                    s += sk[((o*32 + c)*3 + h)*3 + w] * su2[c*3 + h];
            sv2[tid] = s;
        }
        __syncthreads(); blk_l2n(sv2, 96, red);
        if (tid < 96) {
            int c = tid / 3, h = tid % 3; float s = 0.f;
            for (int o = 0; o < 32; o++)
                for (int w = 0; w < 3; w++)
                    s += sk[((o*32 + c)*3 + h)*3 + w] * sv2[o*3 + w];
            su2[tid] = s;
        }
        __syncthreads(); blk_l2n(su2, 96, red);

        if (tid < 32) {
            float s = 0.f;
            for (int j = 0; j < 288; j++) {
                int c = j / 9, h = (j % 9) / 3, w = j % 3;
                s += sk[((tid*32 + c)*3 + h)*3 + w] * su3[j];
            }
            sv3[tid] = s;
        }
        __syncthreads(); blk_l2n(sv3, 32, red);
        if (tid < 288) {
            int c = tid / 9, h = (tid % 9) / 3, w = tid % 3; float s = 0.f;
            for (int o = 0; o < 32; o++)
                s += sk[((o*32 + c)*3 + h)*3 + w] * sv3[o];
            su3[tid] = s;
        }
        __syncthreads(); blk_l2n(su3, 288, red);

        if (tid < 32) {
            float s = 0.f;
            for (int j = 0; j < 288; j++) {
                int o = j / 9, h = (j % 9) / 3, w = j % 3;
                s += sk[((o*32 + tid)*3 + h)*3 + w] * su4[j];
            }
            sv4[tid] = s;
        }
        __syncthreads(); blk_l2n(sv4, 32, red);
        if (tid < 288) {
            int o = tid / 9, h = (tid % 9) / 3, w = tid % 3; float s = 0.f;
            for (int c = 0; c < 32; c++)
                s += sk[((o*32 + c)*3 + h)*3 + w] * sv4[c];
            su4[tid] = s;
        }
        __syncthreads(); blk_l2n(su4, 288, red);
    }

    float p1 = 0.f, p2 = 0.f, p3 = 0.f, p4 = 0.f;
    for (int i = tid; i < 9216; i += 1024) {
        int o = i / 288, r = i % 288;
        int c = r / 9, h = (r % 9) / 3, w = r % 3;
        float k = sk[i];
        p1 += k * su1[c*3 + w]       * sv1[o*3 + h];
        p2 += k * su2[c*3 + h]       * sv2[o*3 + w];
        p3 += k * su3[c*9 + h*3 + w] * sv3[o];
        p4 += k * su4[o*9 + h*3 + w] * sv4[c];
    }
    float s1 = blk_reduce(p1, red), s2 = blk_reduce(p2, red);
    float s3 = blk_reduce(p3, red), s4 = blk_reduce(p4, red);
    float inv = 1.0f / fminf(fminf(s1, s2), fminf(s3, s4));
    for (int i = tid; i < 9216; i += 1024) g_sk[i] = sk[i] * inv;
}

// ---------------------------------------------------------------------------
// Pack 3x3 step weights: step st uses K/(5-st). B[o][k], k = ky*96+kx*32+c.
// ---------------------------------------------------------------------------
__global__ void pack_wm3() {
    int st = blockIdx.x;                       // 0..4
    float inv = 1.0f / (float)(5 - st);
    for (int i = threadIdx.x; i < 2*32*144; i += blockDim.x) {
        int term = i / (32*144);
        int rest = i % (32*144);
        int o = rest / 144, q = rest % 144;
        int k = 2*q;
        int ky = k / 96, kx = (k % 96) / 32, c = k & 31;
        float w0 = g_sk[((o*32 + c    )*3 + ky)*3 + kx] * inv;
        float w1 = g_sk[((o*32 + c + 1)*3 + ky)*3 + kx] * inv;
        uint32_t v;
        if (term == 0) v = pack_split_hi(w0, w1);
        else           v = pack_split_lo(w0, w1);
        g_wm3[((st*2 + term)*32 + o)*WS3 + q] = v;
    }
}

// ---------------------------------------------------------------------------
// x (NCHW fp32) -> channel-last bf16 hi/lo: g_xhi/g_xlo[b][y][x][c]
// ---------------------------------------------------------------------------
__global__ void __launch_bounds__(256) xcvt(const float* __restrict__ x) {
    __shared__ float s[32][257];
    int y = blockIdx.x, b = blockIdx.y, tid = threadIdx.x;
    for (int c = 0; c < 32; c++)
        s[c][tid] = x[(((size_t)b*32 + c)*256 + y)*256 + tid];
    __syncthreads();
    size_t rowbase = (((size_t)b*256 + y)*256) * 32;
    for (int rep = 0; rep < 4; rep++) {
        int u = rep*256 + tid;
        int p = u >> 2, q = u & 3;
        union { unsigned short u16[8]; uint4 v; } hi, lo;
        #pragma unroll
        for (int j = 0; j < 8; j++) {
            float v = s[q*8 + j][p];
            __nv_bfloat16 h = __float2bfloat16(v);
            hi.u16[j] = __bfloat16_as_ushort(h);
            lo.u16[j] = __bfloat16_as_ushort(__float2bfloat16(v - __bfloat162float(h)));
        }
        *(uint4*)(g_xhi + rowbase + (size_t)p*32 + q*8) = hi.v;
        *(uint4*)(g_xlo + rowbase + (size_t)p*32 + q*8) = lo.v;
    }
}

// ---------------------------------------------------------------------------
// One Horner step: out = x + conv3x3(src, K/(5-st))  [circular]
// 512 threads / 16 warps (4 per SMSP — latency fix for R7's occ=12%).
// Warp w: output row (w&1), px range [(w>>1)*32, +32). K=288, 18 k-steps.
// ---------------------------------------------------------------------------
__global__ void __launch_bounds__(512, 1) conv3(
    int src_sel, int dst_sel, int st, int final_step,
    const float* __restrict__ bias, float* __restrict__ out)
{
    extern __shared__ uint32_t dsm[];
    uint32_t* win = dsm;                 // [term][4 rows][258 cols][XS3]
    uint32_t* wsm = dsm + 2*4*WROW3;     // [term][o*WS3+q]

    const int tid  = threadIdx.x;
    const int lane = tid & 31;
    const int wm   = tid >> 5;           // 0..15
    const int r    = wm & 1;             // output row within pair
    const int pxb  = (wm >> 1) * 32;     // px base
    const int b    = blockIdx.x >> 7;
    const int y0   = (blockIdx.x & 127) * 2;

    const uint32_t* shi = sel_hi(src_sel);
    const uint32_t* slo = sel_lo(src_sel);

    // ---- prologue: stage 4 window rows (y0-1 .. y0+2, circular) ----
    {
        const uint4* sh4 = (const uint4*)shi;
        const uint4* sl4 = (const uint4*)slo;
        for (int i = tid; i < 2*4*WCOL3*4; i += 512) {
            int term = i / (4*WCOL3*4);
            int rest = i % (4*WCOL3*4);
            int row  = rest / (WCOL3*4);
            int cc   = (rest % (WCOL3*4)) >> 2;
            int u    = i & 3;
            int ys = (y0 + row - 1) & 255;
            int gx = (cc - 1) & 255;
            size_t sidx = (((size_t)b*256 + ys)*256 + gx)*4 + u;
            uint4 v = (term == 0) ? sh4[sidx] : sl4[sidx];
            *(uint4*)(win + ((term*4 + row)*WCOL3 + cc)*XS3 + u*4) = v;
        }
        const uint32_t* wsrc = g_wm3 + (size_t)st*2*32*WS3;
        for (int i = tid; i < 2*32*144; i += 512) {
            int term = i / (32*144);
            int rest = i % (32*144);
            int o = rest / 144, q = rest % 144;
            wsm[term*WT3 + o*WS3 + q] = wsrc[(term*32 + o)*WS3 + q];
        }
    }
    __syncthreads();

    const uint32_t win_sa = smem_u32(win);
    const uint32_t wsm_sa = smem_u32(wsm);

    float C[2][4][4];
    #pragma unroll
    for (int mf = 0; mf < 2; mf++)
        #pragma unroll
        for (int nf = 0; nf < 4; nf++)
            #pragma unroll
            for (int e = 0; e < 4; e++) C[mf][nf][e] = 0.f;

    // ldmatrix lane addressing (validated R6/R7)
    const int a_row   = (lane & 7) + ((lane >> 3) & 1) * 8;
    const int a_ucol  = (lane >> 4) * 4;
    const int b_n_off = ((lane >> 4) * 8) + (lane & 7);
    const int b_ucol  = ((lane >> 3) & 1) * 4;
    const int qlane = lane & 3;
    const int rlane = lane >> 2;

    // ---- mainloop: 3 ky x 6 k-steps, smem-resident, no syncs ----
    #pragma unroll
    for (int ky = 0; ky < 3; ky++) {
        const int wr = r + ky;                 // window row 0..3
        #pragma unroll
        for (int sub = 0; sub < 6; sub++) {
            const int qb  = (ky*6 + sub)*8;
            const int kx  = sub >> 1;
            const int u0b = (sub & 1) * 8;

            uint32_t bh[4][2], bl[4][2];
            {
                uint32_t f[4];
                #pragma unroll
                for (int p = 0; p < 2; p++) {
                    uint32_t addr = wsm_sa +
                        (((b_n_off + p*16)*WS3) + qb + b_ucol) * 4;
                    ldsm_x4(f, addr);
                    bh[2*p][0] = f[0]; bh[2*p][1] = f[1];
                    bh[2*p+1][0] = f[2]; bh[2*p+1][1] = f[3];
                    ldsm_x4(f, addr + WT3*4);
                    bl[2*p][0] = f[0]; bl[2*p][1] = f[1];
                    bl[2*p+1][0] = f[2]; bl[2*p+1][1] = f[3];
                }
            }

            #pragma unroll
            for (int mf = 0; mf < 2; mf++) {
                int col = pxb + mf*16 + a_row + kx;
                uint32_t offh = (((0*4 + wr)*WCOL3 + col)*XS3 + u0b + a_ucol) * 4;
                uint32_t offl = (((1*4 + wr)*WCOL3 + col)*XS3 + u0b + a_ucol) * 4;
                uint32_t ah[4], al[4];
                ldsm_x4(ah, win_sa + offh);
                ldsm_x4(al, win_sa + offl);
                #pragma unroll
                for (int nf = 0; nf < 4; nf++) {
                    mma_bf16(C[mf][nf], ah, bh[nf]);
                    mma_bf16(C[mf][nf], ah, bl[nf]);
                    mma_bf16(C[mf][nf], al, bh[nf]);
                }
            }
        }
    }

    // ---- epilogue: +x, then store ----
    const uint32_t* xh32 = (const uint32_t*)g_xhi;
    const uint32_t* xl32 = (const uint32_t*)g_xlo;
    const int y = y0 + r;

    if (!final_step) {
        uint32_t* dhi = sel_hi_w(dst_sel);
        uint32_t* dlo = sel_lo_w(dst_sel);
        #pragma unroll
        for (int mf = 0; mf < 2; mf++) {
            #pragma unroll
            for (int half = 0; half < 2; half++) {
                int px = pxb + mf*16 + rlane + half*8;
                size_t base = (((size_t)b*256 + y)*256 + px)*16;
                #pragma unroll
                for (int nf = 0; nf < 4; nf++) {
                    int q = nf*4 + qlane;
                    uint32_t xh = xh32[base + q], xl = xl32[base + q];
                    float v0 = C[mf][nf][half*2 + 0] + bf16_lo(xh) + bf16_lo(xl);
                    float v1 = C[mf][nf][half*2 + 1] + bf16_hi(xh) + bf16_hi(xl);
                    dhi[base + q] = pack_split_hi(v0, v1);
                    dlo[base + q] = pack_split_lo(v0, v1);
                }
            }
        }
    } else {
        #pragma unroll
        for (int mf = 0; mf < 2; mf++) {
            #pragma unroll
            for (int half = 0; half < 2; half++) {
                int px = pxb + mf*16 + rlane + half*8;
                size_t base = (((size_t)b*256 + y)*256 + px)*16;
                #pragma unroll
                for (int nf = 0; nf < 4; nf++) {
                    int q = nf*4 + qlane;
                    int o = 2*q;
                    uint32_t xh = xh32[base + q], xl = xl32[base + q];
                    float v0 = C[mf][nf][half*2 + 0] + bf16_lo(xh) + bf16_lo(xl) + bias[o];
                    float v1 = C[mf][nf][half*2 + 1] + bf16_hi(xh) + bf16_hi(xl) + bias[o + 1];
                    out[((size_t)(b*32 + o    ))*65536 + y*256 + px] = v0;
                    out[((size_t)(b*32 + o + 1))*65536 + y*256 + px] = v1;
                }
            }
        }
    }
}

// ---------------------------------------------------------------------------
// Launcher
// ---------------------------------------------------------------------------
extern "C" void kernel_launch(void* const* d_in, const int* in_sizes, int n_in,
                              void* d_out, int out_size) {
    const float* x    = (const float*)d_in[0];
    const float* raw  = (const float*)d_in[1];
    const float* bias = (const float*)d_in[2];
    const float* u1   = (const float*)d_in[3];
    const float* u2   = (const float*)d_in[4];
    const float* u3   = (const float*)d_in[5];
    const float* u4   = (const float*)d_in[6];
    float* out = (float*)d_out;

    prep_ff<<<1, 1024>>>(raw, u1, u2, u3, u4);
    pack_wm3<<<5, 256>>>();

    dim3 xg(256, 16);
    xcvt<<<xg, 256>>>(x);

    int smem = SM3_U32 * 4;   // 203008 bytes
    cudaFuncSetAttribute(conv3, cudaFuncAttributeMaxDynamicSharedMemorySize, smem);

    // Horner: u4 = x + K/5*x ; u3 = x + K/4*u4 ; u2 = x + K/3*u3 ;
    //         u1 = x + K/2*u2 ; z = x + K*u1 + bias
    conv3<<<2048, 512, smem>>>(0, 1, 0, 0, bias, out);   // x  -> u0  (K/5)
    conv3<<<2048, 512, smem>>>(1, 2, 1, 0, bias, out);   // u0 -> u1  (K/4)
    conv3<<<2048, 512, smem>>>(2, 1, 2, 0, bias, out);   // u1 -> u0  (K/3)
    conv3<<<2048, 512, smem>>>(1, 2, 3, 0, bias, out);   // u0 -> u1  (K/2)
    conv3<<<2048, 512, smem>>>(2, 0, 4, 1, bias, out);   // u1 -> out (K/1)
}

// round 13
// speedup vs baseline: 1.0173x; 1.0173x over previous
#include <cuda_runtime.h>
#include <cuda_bf16.h>
#include <math.h>
#include <stdint.h>

#define CNUM 32
#define KS   3
#define RS   11
#define BAT  16
#define HW   256
#define POWER_IT 3

// 3x3-step GEMM geometry
#define XS3   20                 // u32 stride per window column (16 used)
#define WCOL3 258                // window columns (256 + 2 halo)
#define WROW3 (WCOL3*XS3)        // 5160 u32 per (term,row)
#define WS3   148                // u32 stride per weight row (144 used)
#define WT3   (32*WS3)           // 4736 u32 per weight term
#define SM3_U32 (2*4*WROW3 + 2*WT3)   // 50752 u32 = 203008 B

// ---------------------------------------------------------------------------
// Device scratch
// ---------------------------------------------------------------------------
__device__ float g_sk[CNUM*CNUM*KS*KS];
__device__ __align__(16) unsigned short g_xhi[(size_t)BAT*HW*HW*CNUM];
__device__ __align__(16) unsigned short g_xlo[(size_t)BAT*HW*HW*CNUM];
__device__ __align__(16) unsigned short g_u0h[(size_t)BAT*HW*HW*CNUM];
__device__ __align__(16) unsigned short g_u0l[(size_t)BAT*HW*HW*CNUM];
__device__ __align__(16) unsigned short g_u1h[(size_t)BAT*HW*HW*CNUM];
__device__ __align__(16) unsigned short g_u1l[(size_t)BAT*HW*HW*CNUM];
// 3x3 step weights: [step 0..4][term hi/lo][o=32][WS3 u32]
__device__ uint32_t g_wm3[5*2*32*WS3];

// ---------------------------------------------------------------------------
// MMA / ldmatrix helpers (base-target; validated R5-R7)
// ---------------------------------------------------------------------------
__device__ __forceinline__ void mma_bf16(float* c, const uint32_t* a,
                                         const uint32_t* b) {
    asm volatile(
        "mma.sync.aligned.m16n8k16.row.col.f32.bf16.bf16.f32 "
        "{%0,%1,%2,%3}, {%4,%5,%6,%7}, {%8,%9}, {%0,%1,%2,%3};\n"
        : "+f"(c[0]), "+f"(c[1]), "+f"(c[2]), "+f"(c[3])
        : "r"(a[0]), "r"(a[1]), "r"(a[2]), "r"(a[3]),
          "r"(b[0]), "r"(b[1]));
}
__device__ __forceinline__ void ldsm_x4(uint32_t* r, uint32_t addr) {
    asm volatile(
        "ldmatrix.sync.aligned.m8n8.x4.shared.b16 {%0,%1,%2,%3}, [%4];"
        : "=r"(r[0]), "=r"(r[1]), "=r"(r[2]), "=r"(r[3]) : "r"(addr));
}
__device__ __forceinline__ uint32_t smem_u32(const void* p) {
    uint32_t a;
    asm("{ .reg .u64 t; cvta.to.shared.u64 t, %1; cvt.u32.u64 %0, t; }"
        : "=r"(a) : "l"(p));
    return a;
}
__device__ __forceinline__ float bf16_lo(uint32_t u) {
    return __bfloat162float(__ushort_as_bfloat16((unsigned short)(u & 0xFFFF)));
}
__device__ __forceinline__ float bf16_hi(uint32_t u) {
    return __bfloat162float(__ushort_as_bfloat16((unsigned short)(u >> 16)));
}
__device__ __forceinline__ uint32_t pack_split_hi(float v0, float v1) {
    unsigned short h0 = __bfloat16_as_ushort(__float2bfloat16(v0));
    unsigned short h1 = __bfloat16_as_ushort(__float2bfloat16(v1));
    return (uint32_t)h0 | ((uint32_t)h1 << 16);
}
__device__ __forceinline__ uint32_t pack_split_lo(float v0, float v1) {
    float r0 = v0 - __bfloat162float(__float2bfloat16(v0));
    float r1 = v1 - __bfloat162float(__float2bfloat16(v1));
    unsigned short h0 = __bfloat16_as_ushort(__float2bfloat16(r0));
    unsigned short h1 = __bfloat16_as_ushort(__float2bfloat16(r1));
    return (uint32_t)h0 | ((uint32_t)h1 << 16);
}

__device__ __forceinline__ const uint32_t* sel_hi(int s) {
    return (s == 0) ? (const uint32_t*)g_xhi
         : (s == 1) ? (const uint32_t*)g_u0h : (const uint32_t*)g_u1h;
}
__device__ __forceinline__ const uint32_t* sel_lo(int s) {
    return (s == 0) ? (const uint32_t*)g_xlo
         : (s == 1) ? (const uint32_t*)g_u0l : (const uint32_t*)g_u1l;
}
__device__ __forceinline__ uint32_t* sel_hi_w(int s) {
    return (s == 1) ? (uint32_t*)g_u0h : (uint32_t*)g_u1h;
}
__device__ __forceinline__ uint32_t* sel_lo_w(int s) {
    return (s == 1) ? (uint32_t*)g_u0l : (uint32_t*)g_u1l;
}

// ---------------------------------------------------------------------------
// Block reduce via warp shuffles: 3 syncs instead of 11.
// ---------------------------------------------------------------------------
__device__ __forceinline__ float blk_reduce(float v, float* red) {
    int wid = threadIdx.x >> 5, lane = threadIdx.x & 31;
    #pragma unroll
    for (int o = 16; o; o >>= 1) v += __shfl_down_sync(0xFFFFFFFFu, v, o);
    if (lane == 0) red[wid] = v;
    __syncthreads();
    if (wid == 0) {
        float s = (lane < ((int)blockDim.x >> 5)) ? red[lane] : 0.f;
        #pragma unroll
        for (int o = 16; o; o >>= 1) s += __shfl_down_sync(0xFFFFFFFFu, s, o);
        if (lane == 0) red[0] = s;
    }
    __syncthreads();
    float r = red[0];
    __syncthreads();
    return r;
}
__device__ __forceinline__ void blk_l2n(float* a, int n, float* red) {
    int tid = threadIdx.x;
    float p = 0.f;
    for (int i = tid; i < n; i += 1024) p += a[i] * a[i];
    float s = blk_reduce(p, red);
    float sc = 1.0f / (sqrtf(s) + 1e-12f);
    for (int i = tid; i < n; i += 1024) a[i] *= sc;
    __syncthreads();
}

__global__ void __launch_bounds__(1024) prep_ff(
    const float* __restrict__ raw,
    const float* __restrict__ u1i, const float* __restrict__ u2i,
    const float* __restrict__ u3i, const float* __restrict__ u4i)
{
    __shared__ float sk[CNUM*CNUM*KS*KS];
    __shared__ float su1[96], sv1[96], su2[96], sv2[96];
    __shared__ float su3[288], sv3[32], su4[288], sv4[32];
    __shared__ float red[32];
    int tid = threadIdx.x;

    for (int i = tid; i < 9216; i += 1024) {
        int o = i / 288, r = i % 288;
        int c = r / 9, h = (r % 9) / 3, w = r % 3;
        sk[i] = raw[i] - raw[((c*32 + o)*3 + (2 - h))*3 + (2 - w)];
    }
    if (tid < 96)  su1[tid] = u1i[tid];
    if (tid < 96)  su2[tid] = u2i[tid];
    if (tid < 288) su3[tid] = u3i[tid];
    if (tid < 288) su4[tid] = u4i[tid];
    __syncthreads();

    blk_l2n(su1, 96, red);  blk_l2n(su2, 96, red);
    blk_l2n(su3, 288, red); blk_l2n(su4, 288, red);

    for (int it = 0; it < POWER_IT; it++) {
        if (tid < 96) {
            int o = tid / 3, h = tid % 3; float s = 0.f;
            for (int c = 0; c < 32; c++)
                for (int w = 0; w < 3; w++)
                    s += sk[((o*32 + c)*3 + h)*3 + w] * su1[c*3 + w];
            sv1[tid] = s;
        }
        __syncthreads(); blk_l2n(sv1, 96, red);
        if (tid < 96) {
            int c = tid / 3, w = tid % 3; float s = 0.f;
            for (int o = 0; o < 32; o++)
                for (int h = 0; h < 3; h++)
                    s += sk[((o*32 + c)*3 + h)*3 + w] * sv1[o*3 + h];
            su1[tid] = s;
        }
        __syncthreads(); blk_l2n(su1, 96, red);

        if (tid < 96) {
            int o = tid / 3, w = tid % 3; float s = 0.f;
            for (int c = 0; c < 32; c++)
                for (int h = 0; h < 3; h++)
                    s += sk[((o*32 + c)*3 + h)*3 + w] * su2[c*3 + h];
            sv2[tid] = s;
        }
        __syncthreads(); blk_l2n(sv2, 96, red);
        if (tid < 96) {
            int c = tid / 3, h = tid % 3; float s = 0.f;
            for (int o = 0; o < 32; o++)
                for (int w = 0; w < 3; w++)
                    s += sk[((o*32 + c)*3 + h)*3 + w] * sv2[o*3 + w];
            su2[tid] = s;
        }
        __syncthreads(); blk_l2n(su2, 96, red);

        if (tid < 32) {
            float s = 0.f;
            for (int j = 0; j < 288; j++) {
                int c = j / 9, h = (j % 9) / 3, w = j % 3;
                s += sk[((tid*32 + c)*3 + h)*3 + w] * su3[j];
            }
            sv3[tid] = s;
        }
        __syncthreads(); blk_l2n(sv3, 32, red);
        if (tid < 288) {
            int c = tid / 9, h = (tid % 9) / 3, w = tid % 3; float s = 0.f;
            for (int o = 0; o < 32; o++)
                s += sk[((o*32 + c)*3 + h)*3 + w] * sv3[o];
            su3[tid] = s;
        }
        __syncthreads(); blk_l2n(su3, 288, red);

        if (tid < 32) {
            float s = 0.f;
            for (int j = 0; j < 288; j++) {
                int o = j / 9, h = (j % 9) / 3, w = j % 3;
                s += sk[((o*32 + tid)*3 + h)*3 + w] * su4[j];
            }
            sv4[tid] = s;
        }
        __syncthreads(); blk_l2n(sv4, 32, red);
        if (tid < 288) {
            int o = tid / 9, h = (tid % 9) / 3, w = tid % 3; float s = 0.f;
            for (int c = 0; c < 32; c++)
                s += sk[((o*32 + c)*3 + h)*3 + w] * sv4[c];
            su4[tid] = s;
        }
        __syncthreads(); blk_l2n(su4, 288, red);
    }

    float p1 = 0.f, p2 = 0.f, p3 = 0.f, p4 = 0.f;
    for (int i = tid; i < 9216; i += 1024) {
        int o = i / 288, r = i % 288;
        int c = r / 9, h = (r % 9) / 3, w = r % 3;
        float k = sk[i];
        p1 += k * su1[c*3 + w]       * sv1[o*3 + h];
        p2 += k * su2[c*3 + h]       * sv2[o*3 + w];
        p3 += k * su3[c*9 + h*3 + w] * sv3[o];
        p4 += k * su4[o*9 + h*3 + w] * sv4[c];
    }
    float s1 = blk_reduce(p1, red), s2 = blk_reduce(p2, red);
    float s3 = blk_reduce(p3, red), s4 = blk_reduce(p4, red);
    float inv = 1.0f / fminf(fminf(s1, s2), fminf(s3, s4));
    for (int i = tid; i < 9216; i += 1024) g_sk[i] = sk[i] * inv;
}

// ---------------------------------------------------------------------------
// Pack 3x3 step weights: step st uses K/(5-st). B[o][k], k = ky*96+kx*32+c.
// ---------------------------------------------------------------------------
__global__ void pack_wm3() {
    int st = blockIdx.x;                       // 0..4
    float inv = 1.0f / (float)(5 - st);
    for (int i = threadIdx.x; i < 2*32*144; i += blockDim.x) {
        int term = i / (32*144);
        int rest = i % (32*144);
        int o = rest / 144, q = rest % 144;
        int k = 2*q;
        int ky = k / 96, kx = (k % 96) / 32, c = k & 31;
        float w0 = g_sk[((o*32 + c    )*3 + ky)*3 + kx] * inv;
        float w1 = g_sk[((o*32 + c + 1)*3 + ky)*3 + kx] * inv;
        uint32_t v;
        if (term == 0) v = pack_split_hi(w0, w1);
        else           v = pack_split_lo(w0, w1);
        g_wm3[((st*2 + term)*32 + o)*WS3 + q] = v;
    }
}

// ---------------------------------------------------------------------------
// x (NCHW fp32) -> channel-last bf16 hi/lo: g_xhi/g_xlo[b][y][x][c]
// ---------------------------------------------------------------------------
__global__ void __launch_bounds__(256) xcvt(const float* __restrict__ x) {
    __shared__ float s[32][257];
    int y = blockIdx.x, b = blockIdx.y, tid = threadIdx.x;
    for (int c = 0; c < 32; c++)
        s[c][tid] = x[(((size_t)b*32 + c)*256 + y)*256 + tid];
    __syncthreads();
    size_t rowbase = (((size_t)b*256 + y)*256) * 32;
    for (int rep = 0; rep < 4; rep++) {
        int u = rep*256 + tid;
        int p = u >> 2, q = u & 3;
        union { unsigned short u16[8]; uint4 v; } hi, lo;
        #pragma unroll
        for (int j = 0; j < 8; j++) {
            float v = s[q*8 + j][p];
            __nv_bfloat16 h = __float2bfloat16(v);
            hi.u16[j] = __bfloat16_as_ushort(h);
            lo.u16[j] = __bfloat16_as_ushort(__float2bfloat16(v - __bfloat162float(h)));
        }
        *(uint4*)(g_xhi + rowbase + (size_t)p*32 + q*8) = hi.v;
        *(uint4*)(g_xlo + rowbase + (size_t)p*32 + q*8) = lo.v;
    }
}

// ---------------------------------------------------------------------------
// One Horner step: out = x + conv3x3(src, K/(5-st))  [circular]
// 512 threads / 16 warps (4 per SMSP — latency fix for R7's occ=12%).
// Warp w: output row (w&1), px range [(w>>1)*32, +32). K=288, 18 k-steps.
// ---------------------------------------------------------------------------
__global__ void __launch_bounds__(512, 1) conv3(
    int src_sel, int dst_sel, int st, int final_step,
    const float* __restrict__ bias, float* __restrict__ out)
{
    extern __shared__ uint32_t dsm[];
    uint32_t* win = dsm;                 // [term][4 rows][258 cols][XS3]
    uint32_t* wsm = dsm + 2*4*WROW3;     // [term][o*WS3+q]

    const int tid  = threadIdx.x;
    const int lane = tid & 31;
    const int wm   = tid >> 5;           // 0..15
    const int r    = wm & 1;             // output row within pair
    const int pxb  = (wm >> 1) * 32;     // px base
    const int b    = blockIdx.x >> 7;
    const int y0   = (blockIdx.x & 127) * 2;

    const uint32_t* shi = sel_hi(src_sel);
    const uint32_t* slo = sel_lo(src_sel);

    // ---- prologue: stage 4 window rows (y0-1 .. y0+2, circular) ----
    {
        const uint4* sh4 = (const uint4*)shi;
        const uint4* sl4 = (const uint4*)slo;
        for (int i = tid; i < 2*4*WCOL3*4; i += 512) {
            int term = i / (4*WCOL3*4);
            int rest = i % (4*WCOL3*4);
            int row  = rest / (WCOL3*4);
            int cc   = (rest % (WCOL3*4)) >> 2;
            int u    = i & 3;
            int ys = (y0 + row - 1) & 255;
            int gx = (cc - 1) & 255;
            size_t sidx = (((size_t)b*256 + ys)*256 + gx)*4 + u;
            uint4 v = (term == 0) ? sh4[sidx] : sl4[sidx];
            *(uint4*)(win + ((term*4 + row)*WCOL3 + cc)*XS3 + u*4) = v;
        }
        const uint32_t* wsrc = g_wm3 + (size_t)st*2*32*WS3;
        for (int i = tid; i < 2*32*144; i += 512) {
            int term = i / (32*144);
            int rest = i % (32*144);
            int o = rest / 144, q = rest % 144;
            wsm[term*WT3 + o*WS3 + q] = wsrc[(term*32 + o)*WS3 + q];
        }
    }
    __syncthreads();

    const uint32_t win_sa = smem_u32(win);
    const uint32_t wsm_sa = smem_u32(wsm);

    float C[2][4][4];
    #pragma unroll
    for (int mf = 0; mf < 2; mf++)
        #pragma unroll
        for (int nf = 0; nf < 4; nf++)
            #pragma unroll
            for (int e = 0; e < 4; e++) C[mf][nf][e] = 0.f;

    // ldmatrix lane addressing (validated R6/R7)
    const int a_row   = (lane & 7) + ((lane >> 3) & 1) * 8;
    const int a_ucol  = (lane >> 4) * 4;
    const int b_n_off = ((lane >> 4) * 8) + (lane & 7);
    const int b_ucol  = ((lane >> 3) & 1) * 4;
    const int qlane = lane & 3;
    const int rlane = lane >> 2;

    // ---- mainloop: 3 ky x 6 k-steps, smem-resident, no syncs ----
    #pragma unroll
    for (int ky = 0; ky < 3; ky++) {
        const int wr = r + ky;                 // window row 0..3
        #pragma unroll
        for (int sub = 0; sub < 6; sub++) {
            const int qb  = (ky*6 + sub)*8;
            const int kx  = sub >> 1;
            const int u0b = (sub & 1) * 8;

            uint32_t bh[4][2], bl[4][2];
            {
                uint32_t f[4];
                #pragma unroll
                for (int p = 0; p < 2; p++) {
                    uint32_t addr = wsm_sa +
                        (((b_n_off + p*16)*WS3) + qb + b_ucol) * 4;
                    ldsm_x4(f, addr);
                    bh[2*p][0] = f[0]; bh[2*p][1] = f[1];
                    bh[2*p+1][0] = f[2]; bh[2*p+1][1] = f[3];
                    ldsm_x4(f, addr + WT3*4);
                    bl[2*p][0] = f[0]; bl[2*p][1] = f[1];
                    bl[2*p+1][0] = f[2]; bl[2*p+1][1] = f[3];
                }
            }

            #pragma unroll
            for (int mf = 0; mf < 2; mf++) {
                int col = pxb + mf*16 + a_row + kx;
                uint32_t offh = (((0*4 + wr)*WCOL3 + col)*XS3 + u0b + a_ucol) * 4;
                uint32_t offl = (((1*4 + wr)*WCOL3 + col)*XS3 + u0b + a_ucol) * 4;
                uint32_t ah[4], al[4];
                ldsm_x4(ah, win_sa + offh);
                ldsm_x4(al, win_sa + offl);
                #pragma unroll
                for (int nf = 0; nf < 4; nf++) {
                    mma_bf16(C[mf][nf], ah, bh[nf]);
                    mma_bf16(C[mf][nf], ah, bl[nf]);
                    mma_bf16(C[mf][nf], al, bh[nf]);
                }
            }
        }
    }

    // ---- epilogue: +x, then store ----
    const uint32_t* xh32 = (const uint32_t*)g_xhi;
    const uint32_t* xl32 = (const uint32_t*)g_xlo;
    const int y = y0 + r;

    if (!final_step) {
        uint32_t* dhi = sel_hi_w(dst_sel);
        uint32_t* dlo = sel_lo_w(dst_sel);
        #pragma unroll
        for (int mf = 0; mf < 2; mf++) {
            #pragma unroll
            for (int half = 0; half < 2; half++) {
                int px = pxb + mf*16 + rlane + half*8;
                size_t base = (((size_t)b*256 + y)*256 + px)*16;
                #pragma unroll
                for (int nf = 0; nf < 4; nf++) {
                    int q = nf*4 + qlane;
                    uint32_t xh = xh32[base + q], xl = xl32[base + q];
                    float v0 = C[mf][nf][half*2 + 0] + bf16_lo(xh) + bf16_lo(xl);
                    float v1 = C[mf][nf][half*2 + 1] + bf16_hi(xh) + bf16_hi(xl);
                    dhi[base + q] = pack_split_hi(v0, v1);
                    dlo[base + q] = pack_split_lo(v0, v1);
                }
            }
        }
    } else {
        #pragma unroll
        for (int mf = 0; mf < 2; mf++) {
            #pragma unroll
            for (int half = 0; half < 2; half++) {
                int px = pxb + mf*16 + rlane + half*8;
                size_t base = (((size_t)b*256 + y)*256 + px)*16;
                #pragma unroll
                for (int nf = 0; nf < 4; nf++) {
                    int q = nf*4 + qlane;
                    int o = 2*q;
                    uint32_t xh = xh32[base + q], xl = xl32[base + q];
                    float v0 = C[mf][nf][half*2 + 0] + bf16_lo(xh) + bf16_lo(xl) + bias[o];
                    float v1 = C[mf][nf][half*2 + 1] + bf16_hi(xh) + bf16_hi(xl) + bias[o + 1];
                    out[((size_t)(b*32 + o    ))*65536 + y*256 + px] = v0;
                    out[((size_t)(b*32 + o + 1))*65536 + y*256 + px] = v1;
                }
            }
        }
    }
}

// ---------------------------------------------------------------------------
// Launcher
// ---------------------------------------------------------------------------
extern "C" void kernel_launch(void* const* d_in, const int* in_sizes, int n_in,
                              void* d_out, int out_size) {
    const float* x    = (const float*)d_in[0];
    const float* raw  = (const float*)d_in[1];
    const float* bias = (const float*)d_in[2];
    const float* u1   = (const float*)d_in[3];
    const float* u2   = (const float*)d_in[4];
    const float* u3   = (const float*)d_in[5];
    const float* u4   = (const float*)d_in[6];
    float* out = (float*)d_out;

    prep_ff<<<1, 1024>>>(raw, u1, u2, u3, u4);
    pack_wm3<<<5, 256>>>();

    dim3 xg(256, 16);
    xcvt<<<xg, 256>>>(x);

    int smem = SM3_U32 * 4;   // 203008 bytes
    cudaFuncSetAttribute(conv3, cudaFuncAttributeMaxDynamicSharedMemorySize, smem);

    // Horner: u4 = x + K/5*x ; u3 = x + K/4*u4 ; u2 = x + K/3*u3 ;
    //         u1 = x + K/2*u2 ; z = x + K*u1 + bias
    conv3<<<2048, 512, smem>>>(0, 1, 0, 0, bias, out);   // x  -> u0  (K/5)
    conv3<<<2048, 512, smem>>>(1, 2, 1, 0, bias, out);   // u0 -> u1  (K/4)
    conv3<<<2048, 512, smem>>>(2, 1, 2, 0, bias, out);   // u1 -> u0  (K/3)
    conv3<<<2048, 512, smem>>>(1, 2, 3, 0, bias, out);   // u0 -> u1  (K/2)
    conv3<<<2048, 512, smem>>>(2, 0, 4, 1, bias, out);   // u1 -> out (K/1)
}